// round 1
// baseline (speedup 1.0000x reference)
#include <cuda_runtime.h>
#include <cuda_bf16.h>
#include <math.h>

// Problem constants
#define BB   2
#define SS   2048
#define DD   1024
#define HH   16
#define HDIM 64
#define TOK  (BB * SS)        // 4096 tokens
#define TD   (3 * DD)         // 3072

// ---------------------------------------------------------------------------
// Scratch (allocation-free rule: __device__ globals)
// ---------------------------------------------------------------------------
__device__ float g_qkv[(size_t)TOK * TD];   // [4096, 3072]  48 MB
__device__ float g_ctx[(size_t)TOK * DD];   // [4096, 1024]  16 MB

// ---------------------------------------------------------------------------
// SGEMM: C[M,N] = A[M,K] @ B[K,N] + bias[N]
// 128x128 block tile, BK=8, 256 threads, 8x8 per-thread microtile.
// Requires M%128==0, N%128==0, K%8==0 (true for both uses).
// ---------------------------------------------------------------------------
#define BM 128
#define BN 128
#define BK 8
#define TM 8
#define TN 8

__global__ __launch_bounds__(256)
void sgemm_bias_kernel(const float* __restrict__ A, const float* __restrict__ B,
                       const float* __restrict__ bias, float* __restrict__ C,
                       int M, int N, int K)
{
    __shared__ float As[BK][BM];
    __shared__ float Bs[BK][BN];

    const int bx = blockIdx.x;   // along N
    const int by = blockIdx.y;   // along M
    const int tid = threadIdx.x;
    const int tx = tid & 15;     // 0..15 (N dir)
    const int ty = tid >> 4;     // 0..15 (M dir)

    // A tile loader: 128 rows x 8 cols, 2 threads per row, float4 each
    const int aRow = tid >> 1;          // 0..127
    const int aCol = (tid & 1) * 4;     // 0 or 4
    // B tile loader: 8 rows x 128 cols, 32 threads per row, float4 each
    const int bRow = tid >> 5;          // 0..7
    const int bCol = (tid & 31) * 4;    // 0..124

    const float* Aptr = A + (size_t)(by * BM) * K;
    const float* Bptr = B + bx * BN;

    float acc[TM][TN];
    #pragma unroll
    for (int i = 0; i < TM; i++)
        #pragma unroll
        for (int j = 0; j < TN; j++) acc[i][j] = 0.f;

    for (int k0 = 0; k0 < K; k0 += BK) {
        float4 av = *(const float4*)(Aptr + (size_t)aRow * K + k0 + aCol);
        As[aCol + 0][aRow] = av.x;
        As[aCol + 1][aRow] = av.y;
        As[aCol + 2][aRow] = av.z;
        As[aCol + 3][aRow] = av.w;
        float4 bv = *(const float4*)(Bptr + (size_t)(k0 + bRow) * N + bCol);
        *(float4*)&Bs[bRow][bCol] = bv;
        __syncthreads();

        #pragma unroll
        for (int k = 0; k < BK; k++) {
            float ar[TM], br[TN];
            #pragma unroll
            for (int i = 0; i < TM; i += 4)
                *(float4*)&ar[i] = *(const float4*)&As[k][ty * TM + i];
            #pragma unroll
            for (int j = 0; j < TN; j += 4)
                *(float4*)&br[j] = *(const float4*)&Bs[k][tx * TN + j];
            #pragma unroll
            for (int i = 0; i < TM; i++)
                #pragma unroll
                for (int j = 0; j < TN; j++)
                    acc[i][j] = fmaf(ar[i], br[j], acc[i][j]);
        }
        __syncthreads();
    }

    // epilogue with bias
    #pragma unroll
    for (int i = 0; i < TM; i++) {
        int row = by * BM + ty * TM + i;
        float* cp = C + (size_t)row * N + bx * BN + tx * TN;
        const float* bp = bias + bx * BN + tx * TN;
        #pragma unroll
        for (int j = 0; j < TN; j += 4) {
            float4 o;
            o.x = acc[i][j + 0] + bp[j + 0];
            o.y = acc[i][j + 1] + bp[j + 1];
            o.z = acc[i][j + 2] + bp[j + 2];
            o.w = acc[i][j + 3] + bp[j + 3];
            *(float4*)(cp + j) = o;
        }
    }
}

// ---------------------------------------------------------------------------
// Flash attention, fp32. Grid: (S/64 q-tiles, H, B). 256 threads.
// 64 queries x 64-key tiles, online softmax. 4 threads per query row; each
// thread owns 16 output dims and 16 of 64 scores (interleaved k-rows to avoid
// smem bank conflicts). Q/K/V/P in dynamic smem, pad 68.
// ---------------------------------------------------------------------------
#define APAD 68
#define ATTN_SMEM (4 * 64 * APAD * (int)sizeof(float))   // 69632 bytes

__global__ __launch_bounds__(256)
void flash_attn_kernel(const float* __restrict__ qkv, float* __restrict__ ctx)
{
    extern __shared__ float sh[];
    float* Qs = sh;                  // [64][APAD]
    float* Ks = Qs + 64 * APAD;
    float* Vs = Ks + 64 * APAD;
    float* Ps = Vs + 64 * APAD;

    const int qt = blockIdx.x;
    const int h  = blockIdx.y;
    const int b  = blockIdx.z;
    const int tid = threadIdx.x;
    const int qr  = tid >> 2;        // 0..63 query row
    const int sub = tid & 3;         // 0..3

    const int q_token0 = b * SS + qt * 64;
    const int hoff = h * HDIM;

    // load Q tile
    {
        const int r  = tid >> 4;          // 0..15
        const int c4 = (tid & 15) * 4;    // 0..60
        #pragma unroll
        for (int it = 0; it < 4; it++) {
            int row = it * 16 + r;
            float4 v = *(const float4*)(qkv + (size_t)(q_token0 + row) * TD + hoff + c4);
            *(float4*)&Qs[row * APAD + c4] = v;
        }
    }

    float m = -INFINITY, l = 0.f;
    float acc[16];
    #pragma unroll
    for (int i = 0; i < 16; i++) acc[i] = 0.f;

    const float* qp = &Qs[qr * APAD];

    for (int j = 0; j < SS / 64; j++) {
        const int k_token0 = b * SS + j * 64;
        __syncthreads();   // previous iter's reads of Ks/Vs/Ps done

        // load K and V tiles
        {
            const int r  = tid >> 4;
            const int c4 = (tid & 15) * 4;
            #pragma unroll
            for (int it = 0; it < 4; it++) {
                int row = it * 16 + r;
                size_t base = (size_t)(k_token0 + row) * TD + hoff + c4;
                *(float4*)&Ks[row * APAD + c4] = *(const float4*)(qkv + DD + base);
                *(float4*)&Vs[row * APAD + c4] = *(const float4*)(qkv + 2 * DD + base);
            }
        }
        __syncthreads();

        // scores: this thread handles k-rows kk*4+sub, kk=0..15
        float s[16];
        #pragma unroll
        for (int kk = 0; kk < 16; kk++) s[kk] = 0.f;
        #pragma unroll
        for (int d = 0; d < HDIM; d += 4) {
            float4 qv = *(const float4*)(qp + d);
            #pragma unroll
            for (int kk = 0; kk < 16; kk++) {
                const float4 kv = *(const float4*)(&Ks[(kk * 4 + sub) * APAD + d]);
                s[kk] = fmaf(qv.x, kv.x, s[kk]);
                s[kk] = fmaf(qv.y, kv.y, s[kk]);
                s[kk] = fmaf(qv.z, kv.z, s[kk]);
                s[kk] = fmaf(qv.w, kv.w, s[kk]);
            }
        }
        #pragma unroll
        for (int kk = 0; kk < 16; kk++) s[kk] *= 0.125f;   // HD^-0.5

        // row max (16 local, then across the 4 sub-lanes = consecutive lanes)
        float mloc = s[0];
        #pragma unroll
        for (int kk = 1; kk < 16; kk++) mloc = fmaxf(mloc, s[kk]);
        mloc = fmaxf(mloc, __shfl_xor_sync(0xffffffffu, mloc, 1));
        mloc = fmaxf(mloc, __shfl_xor_sync(0xffffffffu, mloc, 2));
        const float m_new = fmaxf(m, mloc);
        const float alpha = __expf(m - m_new);

        float psum = 0.f;
        #pragma unroll
        for (int kk = 0; kk < 16; kk++) {
            float p = __expf(s[kk] - m_new);
            psum += p;
            Ps[qr * APAD + (kk * 4 + sub)] = p;
        }
        psum += __shfl_xor_sync(0xffffffffu, psum, 1);
        psum += __shfl_xor_sync(0xffffffffu, psum, 2);
        l = l * alpha + psum;
        m = m_new;
        __syncthreads();   // Ps visible to the row's 4 threads

        // O update: this thread owns dims [sub*16, sub*16+16)
        #pragma unroll
        for (int i = 0; i < 16; i++) acc[i] *= alpha;
        const float* pp = &Ps[qr * APAD];
        #pragma unroll 4
        for (int k4 = 0; k4 < 64; k4 += 4) {
            const float4 pv = *(const float4*)(pp + k4);
            const float pks[4] = {pv.x, pv.y, pv.z, pv.w};
            #pragma unroll
            for (int u = 0; u < 4; u++) {
                const float pk = pks[u];
                const float* vp = &Vs[(k4 + u) * APAD + sub * 16];
                #pragma unroll
                for (int i = 0; i < 16; i += 4) {
                    const float4 vv = *(const float4*)(vp + i);
                    acc[i + 0] = fmaf(pk, vv.x, acc[i + 0]);
                    acc[i + 1] = fmaf(pk, vv.y, acc[i + 1]);
                    acc[i + 2] = fmaf(pk, vv.z, acc[i + 2]);
                    acc[i + 3] = fmaf(pk, vv.w, acc[i + 3]);
                }
            }
        }
    }

    // epilogue: ctx[token][h*64 + d] = acc/l
    const float inv_l = 1.f / l;
    float* op = ctx + (size_t)(q_token0 + qr) * DD + hoff + sub * 16;
    #pragma unroll
    for (int i = 0; i < 16; i += 4) {
        float4 o;
        o.x = acc[i + 0] * inv_l;
        o.y = acc[i + 1] * inv_l;
        o.z = acc[i + 2] * inv_l;
        o.w = acc[i + 3] * inv_l;
        *(float4*)(op + i) = o;
    }
}

// ---------------------------------------------------------------------------
// Launch
// ---------------------------------------------------------------------------
extern "C" void kernel_launch(void* const* d_in, const int* in_sizes, int n_in,
                              void* d_out, int out_size)
{
    const float* x     = (const float*)d_in[0];   // [B,S,D]
    const float* Wqkv  = (const float*)d_in[1];   // [D, 3D]
    const float* bqkv  = (const float*)d_in[2];   // [3D]
    const float* Wproj = (const float*)d_in[3];   // [D, D]
    const float* bproj = (const float*)d_in[4];   // [D]
    float* out = (float*)d_out;                   // [B,S,D]

    float* qkvp = nullptr;
    float* ctxp = nullptr;
    cudaGetSymbolAddress((void**)&qkvp, g_qkv);
    cudaGetSymbolAddress((void**)&ctxp, g_ctx);

    static bool attr_set = false;
    if (!attr_set) {
        cudaFuncSetAttribute(flash_attn_kernel,
                             cudaFuncAttributeMaxDynamicSharedMemorySize, ATTN_SMEM);
        attr_set = true;
    }

    // 1) QKV projection: [4096,1024] @ [1024,3072] + bias -> g_qkv
    {
        dim3 grid(TD / BN, TOK / BM);   // (24, 32)
        sgemm_bias_kernel<<<grid, 256>>>(x, Wqkv, bqkv, qkvp, TOK, TD, DD);
    }

    // 2) Attention -> g_ctx  [4096, 1024] in (token, h*64+d) layout
    {
        dim3 grid(SS / 64, HH, BB);     // (32, 16, 2)
        flash_attn_kernel<<<grid, 256, ATTN_SMEM>>>(qkvp, ctxp);
    }

    // 3) Output projection: [4096,1024] @ [1024,1024] + bias -> out
    {
        dim3 grid(DD / BN, TOK / BM);   // (8, 32)
        sgemm_bias_kernel<<<grid, 256>>>(ctxp, Wproj, bproj, out, TOK, DD, DD);
    }
}

// round 2
// speedup vs baseline: 2.1457x; 2.1457x over previous
#include <cuda_runtime.h>
#include <cuda_bf16.h>
#include <math.h>

// Problem constants
#define BB   2
#define SS   2048
#define DD   1024
#define HH   16
#define HDIM 64
#define TOK  (BB * SS)        // 4096 tokens
#define TD   (3 * DD)         // 3072

// ---------------------------------------------------------------------------
// Scratch (allocation-free rule: __device__ globals)
// ---------------------------------------------------------------------------
__device__ float g_qkv[(size_t)TOK * TD];   // [4096, 3072]  48 MB
__device__ float g_ctx[(size_t)TOK * DD];   // [4096, 1024]  16 MB

// ---------------------------------------------------------------------------
// SGEMM: C[M,N] = A[M,K] @ B[K,N] + bias[N]   (unchanged from R1)
// ---------------------------------------------------------------------------
#define BM 128
#define BN 128
#define BK 8
#define TM 8
#define TN 8

__global__ __launch_bounds__(256)
void sgemm_bias_kernel(const float* __restrict__ A, const float* __restrict__ B,
                       const float* __restrict__ bias, float* __restrict__ C,
                       int M, int N, int K)
{
    __shared__ float As[BK][BM];
    __shared__ float Bs[BK][BN];

    const int bx = blockIdx.x;
    const int by = blockIdx.y;
    const int tid = threadIdx.x;
    const int tx = tid & 15;
    const int ty = tid >> 4;

    const int aRow = tid >> 1;
    const int aCol = (tid & 1) * 4;
    const int bRow = tid >> 5;
    const int bCol = (tid & 31) * 4;

    const float* Aptr = A + (size_t)(by * BM) * K;
    const float* Bptr = B + bx * BN;

    float acc[TM][TN];
    #pragma unroll
    for (int i = 0; i < TM; i++)
        #pragma unroll
        for (int j = 0; j < TN; j++) acc[i][j] = 0.f;

    for (int k0 = 0; k0 < K; k0 += BK) {
        float4 av = *(const float4*)(Aptr + (size_t)aRow * K + k0 + aCol);
        As[aCol + 0][aRow] = av.x;
        As[aCol + 1][aRow] = av.y;
        As[aCol + 2][aRow] = av.z;
        As[aCol + 3][aRow] = av.w;
        float4 bv = *(const float4*)(Bptr + (size_t)(k0 + bRow) * N + bCol);
        *(float4*)&Bs[bRow][bCol] = bv;
        __syncthreads();

        #pragma unroll
        for (int k = 0; k < BK; k++) {
            float ar[TM], br[TN];
            #pragma unroll
            for (int i = 0; i < TM; i += 4)
                *(float4*)&ar[i] = *(const float4*)&As[k][ty * TM + i];
            #pragma unroll
            for (int j = 0; j < TN; j += 4)
                *(float4*)&br[j] = *(const float4*)&Bs[k][tx * TN + j];
            #pragma unroll
            for (int i = 0; i < TM; i++)
                #pragma unroll
                for (int j = 0; j < TN; j++)
                    acc[i][j] = fmaf(ar[i], br[j], acc[i][j]);
        }
        __syncthreads();
    }

    #pragma unroll
    for (int i = 0; i < TM; i++) {
        int row = by * BM + ty * TM + i;
        float* cp = C + (size_t)row * N + bx * BN + tx * TN;
        const float* bp = bias + bx * BN + tx * TN;
        #pragma unroll
        for (int j = 0; j < TN; j += 4) {
            float4 o;
            o.x = acc[i][j + 0] + bp[j + 0];
            o.y = acc[i][j + 1] + bp[j + 1];
            o.z = acc[i][j + 2] + bp[j + 2];
            o.w = acc[i][j + 3] + bp[j + 3];
            *(float4*)(cp + j) = o;
        }
    }
}

// ---------------------------------------------------------------------------
// Flash attention v2: register-blocked GEMM structure.
// Block: 256 threads, q-tile 128, k-tile 64. Grid (S/128, H, B).
// Thread grid 16x16. S-phase microtile 8q x 4k (Q,K stored d-major in smem).
// PV-phase microtile 8q x 4d (P row-major [q][k], V row-major [k][d]).
// ---------------------------------------------------------------------------
#define QT   128
#define KT   64
#define QPAD 132   // QsT row length (d-major: [64][132])
#define KPAD 68    // KsT / Vs / Ps row pad

#define ATTN_SMEM ((64 * QPAD + 64 * KPAD + 64 * KPAD + 128 * KPAD) * (int)sizeof(float))

__global__ __launch_bounds__(256, 2)
void flash_attn_v2(const float* __restrict__ qkv, float* __restrict__ ctx)
{
    extern __shared__ float sh[];
    float* QsT = sh;                      // [64][QPAD]  (d-major: QsT[d][q])
    float* KsT = QsT + 64 * QPAD;         // [64][KPAD]  (d-major: KsT[d][k])
    float* Vs  = KsT + 64 * KPAD;         // [64][KPAD]  (k-major: Vs[k][d])
    float* Ps  = Vs  + 64 * KPAD;         // [128][KPAD] (q-major: Ps[q][k])

    const int qt = blockIdx.x;
    const int h  = blockIdx.y;
    const int b  = blockIdx.z;
    const int tid = threadIdx.x;
    const int tx = tid & 15;              // 0..15
    const int ty = tid >> 4;              // 0..15
    const int q0 = ty * 8;                // 8 q rows owned
    const int c0 = tx * 4;                // 4 cols owned (k in S, d in PV)

    const int q_token0 = b * SS + qt * QT;
    const int hoff = h * HDIM;

    // ---- load Q tile transposed: QsT[d][q] ----
    {
        const int r    = tid >> 1;        // 0..127 (q row)
        const int half = tid & 1;         // d half
        const float* gq = qkv + (size_t)(q_token0 + r) * TD + hoff + half * 32;
        #pragma unroll
        for (int u = 0; u < 8; u++) {
            float4 v = *(const float4*)(gq + u * 4);
            const int d = half * 32 + u * 4;
            QsT[(d + 0) * QPAD + r] = v.x;
            QsT[(d + 1) * QPAD + r] = v.y;
            QsT[(d + 2) * QPAD + r] = v.z;
            QsT[(d + 3) * QPAD + r] = v.w;
        }
    }

    float m[8], l[8], acc[8][4];
    #pragma unroll
    for (int i = 0; i < 8; i++) {
        m[i] = -INFINITY; l[i] = 0.f;
        #pragma unroll
        for (int j = 0; j < 4; j++) acc[i][j] = 0.f;
    }

    const int kv_r = tid >> 2;            // 0..63 (k row for loads)
    const int kv_f = tid & 3;             // 0..3

    for (int jt = 0; jt < SS / KT; jt++) {
        const int k_token0 = b * SS + jt * KT;
        __syncthreads();   // protect KsT/Vs/Ps from previous iteration readers

        // ---- load K (transposed) and V tiles ----
        {
            const float* gk = qkv + (size_t)(k_token0 + kv_r) * TD + DD + hoff;
            const float* gv = gk + DD;
            #pragma unroll
            for (int u = 0; u < 4; u++) {
                const int d = kv_f * 4 + u * 16;
                float4 kv4 = *(const float4*)(gk + d);
                KsT[(d + 0) * KPAD + kv_r] = kv4.x;
                KsT[(d + 1) * KPAD + kv_r] = kv4.y;
                KsT[(d + 2) * KPAD + kv_r] = kv4.z;
                KsT[(d + 3) * KPAD + kv_r] = kv4.w;
                *(float4*)&Vs[kv_r * KPAD + d] = *(const float4*)(gv + d);
            }
        }
        __syncthreads();

        // ---- S = Q @ K^T (8x4 microtile, outer product over d) ----
        float s[8][4];
        #pragma unroll
        for (int i = 0; i < 8; i++)
            #pragma unroll
            for (int j = 0; j < 4; j++) s[i][j] = 0.f;

        #pragma unroll 8
        for (int d = 0; d < HDIM; d++) {
            float qr[8], kr[4];
            *(float4*)&qr[0] = *(const float4*)&QsT[d * QPAD + q0];
            *(float4*)&qr[4] = *(const float4*)&QsT[d * QPAD + q0 + 4];
            *(float4*)&kr[0] = *(const float4*)&KsT[d * KPAD + c0];
            #pragma unroll
            for (int i = 0; i < 8; i++)
                #pragma unroll
                for (int j = 0; j < 4; j++)
                    s[i][j] = fmaf(qr[i], kr[j], s[i][j]);
        }

        // ---- online softmax (rows replicated across the 16 tx threads) ----
        float alpha[8];
        #pragma unroll
        for (int i = 0; i < 8; i++) {
            float mx = s[i][0];
            #pragma unroll
            for (int j = 1; j < 4; j++) mx = fmaxf(mx, s[i][j]);
            mx *= 0.125f;
            mx = fmaxf(mx, __shfl_xor_sync(0xffffffffu, mx, 1));
            mx = fmaxf(mx, __shfl_xor_sync(0xffffffffu, mx, 2));
            mx = fmaxf(mx, __shfl_xor_sync(0xffffffffu, mx, 4));
            mx = fmaxf(mx, __shfl_xor_sync(0xffffffffu, mx, 8));
            const float m_new = fmaxf(m[i], mx);
            alpha[i] = __expf(m[i] - m_new);

            float p[4], ps = 0.f;
            #pragma unroll
            for (int j = 0; j < 4; j++) {
                p[j] = __expf(fmaf(s[i][j], 0.125f, -m_new));
                ps += p[j];
            }
            ps += __shfl_xor_sync(0xffffffffu, ps, 1);
            ps += __shfl_xor_sync(0xffffffffu, ps, 2);
            ps += __shfl_xor_sync(0xffffffffu, ps, 4);
            ps += __shfl_xor_sync(0xffffffffu, ps, 8);
            l[i] = l[i] * alpha[i] + ps;
            m[i] = m_new;

            float4 pv4 = make_float4(p[0], p[1], p[2], p[3]);
            *(float4*)&Ps[(q0 + i) * KPAD + c0] = pv4;
        }

        // rescale accumulators
        #pragma unroll
        for (int i = 0; i < 8; i++)
            #pragma unroll
            for (int j = 0; j < 4; j++) acc[i][j] *= alpha[i];

        __syncthreads();   // Ps fully written

        // ---- O += P @ V (8x4 microtile, k unrolled by 4) ----
        #pragma unroll 4
        for (int k = 0; k < KT; k += 4) {
            float vr[4][4];
            #pragma unroll
            for (int u = 0; u < 4; u++)
                *(float4*)&vr[u][0] = *(const float4*)&Vs[(k + u) * KPAD + c0];
            #pragma unroll
            for (int i = 0; i < 8; i++) {
                float pr[4];
                *(float4*)&pr[0] = *(const float4*)&Ps[(q0 + i) * KPAD + k];
                #pragma unroll
                for (int u = 0; u < 4; u++) {
                    #pragma unroll
                    for (int j = 0; j < 4; j++)
                        acc[i][j] = fmaf(pr[u], vr[u][j], acc[i][j]);
                }
            }
        }
    }

    // ---- epilogue: ctx[token][h*64 + d] = acc / l ----
    #pragma unroll
    for (int i = 0; i < 8; i++) {
        const float inv_l = 1.f / l[i];
        float* op = ctx + (size_t)(q_token0 + q0 + i) * DD + hoff + c0;
        float4 o;
        o.x = acc[i][0] * inv_l;
        o.y = acc[i][1] * inv_l;
        o.z = acc[i][2] * inv_l;
        o.w = acc[i][3] * inv_l;
        *(float4*)op = o;
    }
}

// ---------------------------------------------------------------------------
// Launch
// ---------------------------------------------------------------------------
extern "C" void kernel_launch(void* const* d_in, const int* in_sizes, int n_in,
                              void* d_out, int out_size)
{
    const float* x     = (const float*)d_in[0];
    const float* Wqkv  = (const float*)d_in[1];
    const float* bqkv  = (const float*)d_in[2];
    const float* Wproj = (const float*)d_in[3];
    const float* bproj = (const float*)d_in[4];
    float* out = (float*)d_out;

    float* qkvp = nullptr;
    float* ctxp = nullptr;
    cudaGetSymbolAddress((void**)&qkvp, g_qkv);
    cudaGetSymbolAddress((void**)&ctxp, g_ctx);

    static bool attr_set = false;
    if (!attr_set) {
        cudaFuncSetAttribute(flash_attn_v2,
                             cudaFuncAttributeMaxDynamicSharedMemorySize, ATTN_SMEM);
        attr_set = true;
    }

    // 1) QKV projection
    {
        dim3 grid(TD / BN, TOK / BM);
        sgemm_bias_kernel<<<grid, 256>>>(x, Wqkv, bqkv, qkvp, TOK, TD, DD);
    }

    // 2) Attention
    {
        dim3 grid(SS / QT, HH, BB);     // (16, 16, 2)
        flash_attn_v2<<<grid, 256, ATTN_SMEM>>>(qkvp, ctxp);
    }

    // 3) Output projection
    {
        dim3 grid(DD / BN, TOK / BM);
        sgemm_bias_kernel<<<grid, 256>>>(ctxp, Wproj, bproj, out, TOK, DD, DD);
    }
}

// round 5
// speedup vs baseline: 3.1239x; 1.4559x over previous
#include <cuda_runtime.h>
#include <cuda_bf16.h>
#include <math.h>
#include <stdint.h>

// Problem constants
#define BB   2
#define SS   2048
#define DD   1024
#define HH   16
#define HDIM 64
#define TOK  (BB * SS)        // 4096 tokens
#define TD   (3 * DD)         // 3072

// ---------------------------------------------------------------------------
// Scratch
// ---------------------------------------------------------------------------
__device__ float g_qkv[(size_t)TOK * TD];   // 48 MB
__device__ float g_ctx[(size_t)TOK * DD];   // 16 MB

// ---------------------------------------------------------------------------
// mma.sync tf32 GEMM + bias: C[M,N] = A[M,K] @ B[K,N] + bias[N]
// CTA 128x128, BK=32, 256 threads = 8 warps (2M x 4N), warp tile 64x32.
// m16n8k8 tf32 MMA, inputs converted with cvt.rna (round-to-nearest) to
// keep the error zero-mean. Double-buffered smem, 1 syncthreads/chunk.
// Requires M%128==0, N%128==0, K%32==0.
// ---------------------------------------------------------------------------
#define GBM 128
#define GBN 128
#define GBK 32
#define ASTR 36     // A smem row stride (fp32 words): bank = 4r + c, conflict-free
#define BSTR 136    // B smem row stride: bank = 8k + n, conflict-free

#define A_BUF_W (GBM * ASTR)          // 4608 words
#define B_BUF_W (GBK * BSTR)          // 4352 words
#define GEMM_SMEM_W (2 * A_BUF_W + 2 * B_BUF_W + GBN)
#define GEMM_SMEM_B (GEMM_SMEM_W * 4) // 72192 bytes

__device__ __forceinline__ uint32_t f2tf32(float v) {
    uint32_t r;
    asm("cvt.rna.tf32.f32 %0, %1;" : "=r"(r) : "f"(v));
    return r;
}

__device__ __forceinline__ void mma_tf32(float* d, const uint32_t* a, const uint32_t* b) {
    asm volatile(
        "mma.sync.aligned.m16n8k8.row.col.f32.tf32.tf32.f32 "
        "{%0,%1,%2,%3}, {%4,%5,%6,%7}, {%8,%9}, {%0,%1,%2,%3};"
        : "+f"(d[0]), "+f"(d[1]), "+f"(d[2]), "+f"(d[3])
        : "r"(a[0]), "r"(a[1]), "r"(a[2]), "r"(a[3]), "r"(b[0]), "r"(b[1]));
}

__global__ __launch_bounds__(256)
void mma_gemm_bias(const float* __restrict__ A, const float* __restrict__ B,
                   const float* __restrict__ bias, float* __restrict__ C,
                   int M, int N, int K)
{
    extern __shared__ uint32_t smw[];
    uint32_t* As = smw;                        // 2 x [128][36]
    uint32_t* Bs = smw + 2 * A_BUF_W;          // 2 x [32][136]
    float* biass = (float*)(smw + 2 * A_BUF_W + 2 * B_BUF_W);

    const int tid  = threadIdx.x;
    const int wid  = tid >> 5;
    const int lane = tid & 31;
    const int wm   = wid & 1;       // 0..1  M direction (64 rows each)
    const int wn   = wid >> 1;      // 0..3  N direction (32 cols each)
    const int bx   = blockIdx.x;    // N tile
    const int by   = blockIdx.y;    // M tile

    if (tid < GBN) biass[tid] = bias[bx * GBN + tid];

    // loader mapping
    const int ar = tid >> 1;              // A row 0..127 (2 threads/row)
    const int af0 = (tid & 1) * 16;       // A col base (16 floats each)
    const int br = tid >> 3;              // B k-row 0..31 (8 threads/row)
    const int bf0 = (tid & 7) * 4;        // B col base within 32-float stripes

    const float* Ag = A + (size_t)(by * GBM) * K;
    const float* Bg = B + bx * GBN;

    float4 aR[4], bR[4];

    // ---- prologue: load + store chunk 0 ----
    {
        const float* ap = Ag + (size_t)ar * K + af0;
        #pragma unroll
        for (int j = 0; j < 4; j++) aR[j] = *(const float4*)(ap + j * 4);
        const float* bp = Bg + (size_t)br * N + bf0;
        #pragma unroll
        for (int j = 0; j < 4; j++) bR[j] = *(const float4*)(bp + j * 32);

        uint32_t* ad = As + ar * ASTR + af0;
        #pragma unroll
        for (int j = 0; j < 4; j++) {
            ad[j*4+0] = f2tf32(aR[j].x); ad[j*4+1] = f2tf32(aR[j].y);
            ad[j*4+2] = f2tf32(aR[j].z); ad[j*4+3] = f2tf32(aR[j].w);
        }
        uint32_t* bd = Bs + br * BSTR + bf0;
        #pragma unroll
        for (int j = 0; j < 4; j++) {
            bd[j*32+0] = f2tf32(bR[j].x); bd[j*32+1] = f2tf32(bR[j].y);
            bd[j*32+2] = f2tf32(bR[j].z); bd[j*32+3] = f2tf32(bR[j].w);
        }
    }
    __syncthreads();

    float acc[4][4][4];
    #pragma unroll
    for (int mi = 0; mi < 4; mi++)
        #pragma unroll
        for (int ni = 0; ni < 4; ni++)
            #pragma unroll
            for (int v = 0; v < 4; v++) acc[mi][ni][v] = 0.f;

    const int nchunks = K / GBK;
    const int fr = lane >> 2;      // fragment row group 0..7
    const int fc = lane & 3;       // fragment col group 0..3

    for (int c = 0; c < nchunks; c++) {
        // stage next chunk's gmem loads
        if (c + 1 < nchunks) {
            const int k0 = (c + 1) * GBK;
            const float* ap = Ag + (size_t)ar * K + k0 + af0;
            #pragma unroll
            for (int j = 0; j < 4; j++) aR[j] = *(const float4*)(ap + j * 4);
            const float* bp = Bg + (size_t)(k0 + br) * N + bf0;
            #pragma unroll
            for (int j = 0; j < 4; j++) bR[j] = *(const float4*)(bp + j * 32);
        }

        // ---- compute on buffer c&1 ----
        {
            const uint32_t* Ab = As + (c & 1) * A_BUF_W + (wm * 64) * ASTR;
            const uint32_t* Bb = Bs + (c & 1) * B_BUF_W + wn * 32;
            #pragma unroll
            for (int ks = 0; ks < 4; ks++) {
                const int k = ks * 8 + fc;
                uint32_t afr[4][4], bfr[4][2];
                #pragma unroll
                for (int mi = 0; mi < 4; mi++) {
                    const uint32_t* p = Ab + (mi * 16 + fr) * ASTR + k;
                    afr[mi][0] = p[0];
                    afr[mi][1] = p[8 * ASTR];
                    afr[mi][2] = p[4];
                    afr[mi][3] = p[8 * ASTR + 4];
                }
                #pragma unroll
                for (int ni = 0; ni < 4; ni++) {
                    const uint32_t* q = Bb + k * BSTR + ni * 8 + fr;
                    bfr[ni][0] = q[0];
                    bfr[ni][1] = q[4 * BSTR];
                }
                #pragma unroll
                for (int mi = 0; mi < 4; mi++)
                    #pragma unroll
                    for (int ni = 0; ni < 4; ni++)
                        mma_tf32(acc[mi][ni], afr[mi], bfr[ni]);
            }
        }

        // ---- store staged chunk into the other buffer ----
        if (c + 1 < nchunks) {
            uint32_t* ad = As + ((c + 1) & 1) * A_BUF_W + ar * ASTR + af0;
            #pragma unroll
            for (int j = 0; j < 4; j++) {
                ad[j*4+0] = f2tf32(aR[j].x); ad[j*4+1] = f2tf32(aR[j].y);
                ad[j*4+2] = f2tf32(aR[j].z); ad[j*4+3] = f2tf32(aR[j].w);
            }
            uint32_t* bd = Bs + ((c + 1) & 1) * B_BUF_W + br * BSTR + bf0;
            #pragma unroll
            for (int j = 0; j < 4; j++) {
                bd[j*32+0] = f2tf32(bR[j].x); bd[j*32+1] = f2tf32(bR[j].y);
                bd[j*32+2] = f2tf32(bR[j].z); bd[j*32+3] = f2tf32(bR[j].w);
            }
            __syncthreads();
        }
    }

    // ---- epilogue: acc + bias -> C ----
    #pragma unroll
    for (int mi = 0; mi < 4; mi++) {
        const int row = by * GBM + wm * 64 + mi * 16 + fr;
        #pragma unroll
        for (int ni = 0; ni < 4; ni++) {
            const int lcol = wn * 32 + ni * 8 + fc * 2;
            const int col  = bx * GBN + lcol;
            float2 o0, o1;
            o0.x = acc[mi][ni][0] + biass[lcol];
            o0.y = acc[mi][ni][1] + biass[lcol + 1];
            o1.x = acc[mi][ni][2] + biass[lcol];
            o1.y = acc[mi][ni][3] + biass[lcol + 1];
            *(float2*)(C + (size_t)row * N + col)       = o0;
            *(float2*)(C + (size_t)(row + 8) * N + col) = o1;
        }
    }
}

// ---------------------------------------------------------------------------
// Flash attention v2 (unchanged from R2)
// ---------------------------------------------------------------------------
#define QT   128
#define KT   64
#define QPAD 132
#define KPAD 68
#define ATTN_SMEM ((64 * QPAD + 64 * KPAD + 64 * KPAD + 128 * KPAD) * (int)sizeof(float))

__global__ __launch_bounds__(256, 2)
void flash_attn_v2(const float* __restrict__ qkv, float* __restrict__ ctx)
{
    extern __shared__ float sh[];
    float* QsT = sh;
    float* KsT = QsT + 64 * QPAD;
    float* Vs  = KsT + 64 * KPAD;
    float* Ps  = Vs  + 64 * KPAD;

    const int qt = blockIdx.x;
    const int h  = blockIdx.y;
    const int b  = blockIdx.z;
    const int tid = threadIdx.x;
    const int tx = tid & 15;
    const int ty = tid >> 4;
    const int q0 = ty * 8;
    const int c0 = tx * 4;

    const int q_token0 = b * SS + qt * QT;
    const int hoff = h * HDIM;

    {
        const int r    = tid >> 1;
        const int half = tid & 1;
        const float* gq = qkv + (size_t)(q_token0 + r) * TD + hoff + half * 32;
        #pragma unroll
        for (int u = 0; u < 8; u++) {
            float4 v = *(const float4*)(gq + u * 4);
            const int d = half * 32 + u * 4;
            QsT[(d + 0) * QPAD + r] = v.x;
            QsT[(d + 1) * QPAD + r] = v.y;
            QsT[(d + 2) * QPAD + r] = v.z;
            QsT[(d + 3) * QPAD + r] = v.w;
        }
    }

    float m[8], l[8], acc[8][4];
    #pragma unroll
    for (int i = 0; i < 8; i++) {
        m[i] = -INFINITY; l[i] = 0.f;
        #pragma unroll
        for (int j = 0; j < 4; j++) acc[i][j] = 0.f;
    }

    const int kv_r = tid >> 2;
    const int kv_f = tid & 3;

    for (int jt = 0; jt < SS / KT; jt++) {
        const int k_token0 = b * SS + jt * KT;
        __syncthreads();

        {
            const float* gk = qkv + (size_t)(k_token0 + kv_r) * TD + DD + hoff;
            const float* gv = gk + DD;
            #pragma unroll
            for (int u = 0; u < 4; u++) {
                const int d = kv_f * 4 + u * 16;
                float4 kv4 = *(const float4*)(gk + d);
                KsT[(d + 0) * KPAD + kv_r] = kv4.x;
                KsT[(d + 1) * KPAD + kv_r] = kv4.y;
                KsT[(d + 2) * KPAD + kv_r] = kv4.z;
                KsT[(d + 3) * KPAD + kv_r] = kv4.w;
                *(float4*)&Vs[kv_r * KPAD + d] = *(const float4*)(gv + d);
            }
        }
        __syncthreads();

        float s[8][4];
        #pragma unroll
        for (int i = 0; i < 8; i++)
            #pragma unroll
            for (int j = 0; j < 4; j++) s[i][j] = 0.f;

        #pragma unroll 8
        for (int d = 0; d < HDIM; d++) {
            float qr[8], kr[4];
            *(float4*)&qr[0] = *(const float4*)&QsT[d * QPAD + q0];
            *(float4*)&qr[4] = *(const float4*)&QsT[d * QPAD + q0 + 4];
            *(float4*)&kr[0] = *(const float4*)&KsT[d * KPAD + c0];
            #pragma unroll
            for (int i = 0; i < 8; i++)
                #pragma unroll
                for (int j = 0; j < 4; j++)
                    s[i][j] = fmaf(qr[i], kr[j], s[i][j]);
        }

        float alpha[8];
        #pragma unroll
        for (int i = 0; i < 8; i++) {
            float mx = s[i][0];
            #pragma unroll
            for (int j = 1; j < 4; j++) mx = fmaxf(mx, s[i][j]);
            mx *= 0.125f;
            mx = fmaxf(mx, __shfl_xor_sync(0xffffffffu, mx, 1));
            mx = fmaxf(mx, __shfl_xor_sync(0xffffffffu, mx, 2));
            mx = fmaxf(mx, __shfl_xor_sync(0xffffffffu, mx, 4));
            mx = fmaxf(mx, __shfl_xor_sync(0xffffffffu, mx, 8));
            const float m_new = fmaxf(m[i], mx);
            alpha[i] = __expf(m[i] - m_new);

            float p[4], ps = 0.f;
            #pragma unroll
            for (int j = 0; j < 4; j++) {
                p[j] = __expf(fmaf(s[i][j], 0.125f, -m_new));
                ps += p[j];
            }
            ps += __shfl_xor_sync(0xffffffffu, ps, 1);
            ps += __shfl_xor_sync(0xffffffffu, ps, 2);
            ps += __shfl_xor_sync(0xffffffffu, ps, 4);
            ps += __shfl_xor_sync(0xffffffffu, ps, 8);
            l[i] = l[i] * alpha[i] + ps;
            m[i] = m_new;

            float4 pv4 = make_float4(p[0], p[1], p[2], p[3]);
            *(float4*)&Ps[(q0 + i) * KPAD + c0] = pv4;
        }

        #pragma unroll
        for (int i = 0; i < 8; i++)
            #pragma unroll
            for (int j = 0; j < 4; j++) acc[i][j] *= alpha[i];

        __syncthreads();

        #pragma unroll 4
        for (int k = 0; k < KT; k += 4) {
            float vr[4][4];
            #pragma unroll
            for (int u = 0; u < 4; u++)
                *(float4*)&vr[u][0] = *(const float4*)&Vs[(k + u) * KPAD + c0];
            #pragma unroll
            for (int i = 0; i < 8; i++) {
                float pr[4];
                *(float4*)&pr[0] = *(const float4*)&Ps[(q0 + i) * KPAD + k];
                #pragma unroll
                for (int u = 0; u < 4; u++) {
                    #pragma unroll
                    for (int j = 0; j < 4; j++)
                        acc[i][j] = fmaf(pr[u], vr[u][j], acc[i][j]);
                }
            }
        }
    }

    #pragma unroll
    for (int i = 0; i < 8; i++) {
        const float inv_l = 1.f / l[i];
        float* op = ctx + (size_t)(q_token0 + q0 + i) * DD + hoff + c0;
        float4 o;
        o.x = acc[i][0] * inv_l;
        o.y = acc[i][1] * inv_l;
        o.z = acc[i][2] * inv_l;
        o.w = acc[i][3] * inv_l;
        *(float4*)op = o;
    }
}

// ---------------------------------------------------------------------------
// Launch
// ---------------------------------------------------------------------------
extern "C" void kernel_launch(void* const* d_in, const int* in_sizes, int n_in,
                              void* d_out, int out_size)
{
    const float* x     = (const float*)d_in[0];
    const float* Wqkv  = (const float*)d_in[1];
    const float* bqkv  = (const float*)d_in[2];
    const float* Wproj = (const float*)d_in[3];
    const float* bproj = (const float*)d_in[4];
    float* out = (float*)d_out;

    float* qkvp = nullptr;
    float* ctxp = nullptr;
    cudaGetSymbolAddress((void**)&qkvp, g_qkv);
    cudaGetSymbolAddress((void**)&ctxp, g_ctx);

    static bool attr_set = false;
    if (!attr_set) {
        cudaFuncSetAttribute(flash_attn_v2,
                             cudaFuncAttributeMaxDynamicSharedMemorySize, ATTN_SMEM);
        cudaFuncSetAttribute(mma_gemm_bias,
                             cudaFuncAttributeMaxDynamicSharedMemorySize, GEMM_SMEM_B);
        attr_set = true;
    }

    // 1) QKV projection: [4096,1024] @ [1024,3072] + bias
    {
        dim3 grid(TD / GBN, TOK / GBM);   // (24, 32)
        mma_gemm_bias<<<grid, 256, GEMM_SMEM_B>>>(x, Wqkv, bqkv, qkvp, TOK, TD, DD);
    }

    // 2) Attention
    {
        dim3 grid(SS / QT, HH, BB);       // (16, 16, 2)
        flash_attn_v2<<<grid, 256, ATTN_SMEM>>>(qkvp, ctxp);
    }

    // 3) Output projection: [4096,1024] @ [1024,1024] + bias
    {
        dim3 grid(DD / GBN, TOK / GBM);   // (8, 32)
        mma_gemm_bias<<<grid, 256, GEMM_SMEM_B>>>(ctxp, Wproj, bproj, out, TOK, DD, DD);
    }
}

// round 12
// speedup vs baseline: 4.8671x; 1.5580x over previous
#include <cuda_runtime.h>
#include <cuda_bf16.h>
#include <math.h>
#include <stdint.h>

// Problem constants
#define BB   2
#define SS   2048
#define DD   1024
#define HH   16
#define HDIM 64
#define TOK  (BB * SS)        // 4096 tokens
#define TD   (3 * DD)         // 3072

// ---------------------------------------------------------------------------
// Scratch
// ---------------------------------------------------------------------------
__device__ float g_qkv[(size_t)TOK * TD];   // 48 MB
__device__ float g_ctx[(size_t)TOK * DD];   // 16 MB

__device__ __forceinline__ uint32_t f2tf32(float v) {
    uint32_t r;
    asm("cvt.rna.tf32.f32 %0, %1;" : "=r"(r) : "f"(v));
    return r;
}

__device__ __forceinline__ void mma_tf32(float* d, const uint32_t* a, const uint32_t* b) {
    asm volatile(
        "mma.sync.aligned.m16n8k8.row.col.f32.tf32.tf32.f32 "
        "{%0,%1,%2,%3}, {%4,%5,%6,%7}, {%8,%9}, {%0,%1,%2,%3};"
        : "+f"(d[0]), "+f"(d[1]), "+f"(d[2]), "+f"(d[3])
        : "r"(a[0]), "r"(a[1]), "r"(a[2]), "r"(a[3]), "r"(b[0]), "r"(b[1]));
}

// ---------------------------------------------------------------------------
// mma.sync tf32 GEMM + bias (unchanged from R5)
// ---------------------------------------------------------------------------
#define GBM 128
#define GBN 128
#define GBK 32
#define ASTR 36
#define BSTR 136

#define A_BUF_W (GBM * ASTR)
#define B_BUF_W (GBK * BSTR)
#define GEMM_SMEM_W (2 * A_BUF_W + 2 * B_BUF_W + GBN)
#define GEMM_SMEM_B (GEMM_SMEM_W * 4)

__global__ __launch_bounds__(256)
void mma_gemm_bias(const float* __restrict__ A, const float* __restrict__ B,
                   const float* __restrict__ bias, float* __restrict__ C,
                   int M, int N, int K)
{
    extern __shared__ uint32_t smw[];
    uint32_t* As = smw;
    uint32_t* Bs = smw + 2 * A_BUF_W;
    float* biass = (float*)(smw + 2 * A_BUF_W + 2 * B_BUF_W);

    const int tid  = threadIdx.x;
    const int wid  = tid >> 5;
    const int lane = tid & 31;
    const int wm   = wid & 1;
    const int wn   = wid >> 1;
    const int bx   = blockIdx.x;
    const int by   = blockIdx.y;

    if (tid < GBN) biass[tid] = bias[bx * GBN + tid];

    const int ar = tid >> 1;
    const int af0 = (tid & 1) * 16;
    const int br = tid >> 3;
    const int bf0 = (tid & 7) * 4;

    const float* Ag = A + (size_t)(by * GBM) * K;
    const float* Bg = B + bx * GBN;

    float4 aR[4], bR[4];

    {
        const float* ap = Ag + (size_t)ar * K + af0;
        #pragma unroll
        for (int j = 0; j < 4; j++) aR[j] = *(const float4*)(ap + j * 4);
        const float* bp = Bg + (size_t)br * N + bf0;
        #pragma unroll
        for (int j = 0; j < 4; j++) bR[j] = *(const float4*)(bp + j * 32);

        uint32_t* ad = As + ar * ASTR + af0;
        #pragma unroll
        for (int j = 0; j < 4; j++) {
            ad[j*4+0] = f2tf32(aR[j].x); ad[j*4+1] = f2tf32(aR[j].y);
            ad[j*4+2] = f2tf32(aR[j].z); ad[j*4+3] = f2tf32(aR[j].w);
        }
        uint32_t* bd = Bs + br * BSTR + bf0;
        #pragma unroll
        for (int j = 0; j < 4; j++) {
            bd[j*32+0] = f2tf32(bR[j].x); bd[j*32+1] = f2tf32(bR[j].y);
            bd[j*32+2] = f2tf32(bR[j].z); bd[j*32+3] = f2tf32(bR[j].w);
        }
    }
    __syncthreads();

    float acc[4][4][4];
    #pragma unroll
    for (int mi = 0; mi < 4; mi++)
        #pragma unroll
        for (int ni = 0; ni < 4; ni++)
            #pragma unroll
            for (int v = 0; v < 4; v++) acc[mi][ni][v] = 0.f;

    const int nchunks = K / GBK;
    const int fr = lane >> 2;
    const int fc = lane & 3;

    for (int c = 0; c < nchunks; c++) {
        if (c + 1 < nchunks) {
            const int k0 = (c + 1) * GBK;
            const float* ap = Ag + (size_t)ar * K + k0 + af0;
            #pragma unroll
            for (int j = 0; j < 4; j++) aR[j] = *(const float4*)(ap + j * 4);
            const float* bp = Bg + (size_t)(k0 + br) * N + bf0;
            #pragma unroll
            for (int j = 0; j < 4; j++) bR[j] = *(const float4*)(bp + j * 32);
        }

        {
            const uint32_t* Ab = As + (c & 1) * A_BUF_W + (wm * 64) * ASTR;
            const uint32_t* Bb = Bs + (c & 1) * B_BUF_W + wn * 32;
            #pragma unroll
            for (int ks = 0; ks < 4; ks++) {
                const int k = ks * 8 + fc;
                uint32_t afr[4][4], bfr[4][2];
                #pragma unroll
                for (int mi = 0; mi < 4; mi++) {
                    const uint32_t* p = Ab + (mi * 16 + fr) * ASTR + k;
                    afr[mi][0] = p[0];
                    afr[mi][1] = p[8 * ASTR];
                    afr[mi][2] = p[4];
                    afr[mi][3] = p[8 * ASTR + 4];
                }
                #pragma unroll
                for (int ni = 0; ni < 4; ni++) {
                    const uint32_t* q = Bb + k * BSTR + ni * 8 + fr;
                    bfr[ni][0] = q[0];
                    bfr[ni][1] = q[4 * BSTR];
                }
                #pragma unroll
                for (int mi = 0; mi < 4; mi++)
                    #pragma unroll
                    for (int ni = 0; ni < 4; ni++)
                        mma_tf32(acc[mi][ni], afr[mi], bfr[ni]);
            }
        }

        if (c + 1 < nchunks) {
            uint32_t* ad = As + ((c + 1) & 1) * A_BUF_W + ar * ASTR + af0;
            #pragma unroll
            for (int j = 0; j < 4; j++) {
                ad[j*4+0] = f2tf32(aR[j].x); ad[j*4+1] = f2tf32(aR[j].y);
                ad[j*4+2] = f2tf32(aR[j].z); ad[j*4+3] = f2tf32(aR[j].w);
            }
            uint32_t* bd = Bs + ((c + 1) & 1) * B_BUF_W + br * BSTR + bf0;
            #pragma unroll
            for (int j = 0; j < 4; j++) {
                bd[j*32+0] = f2tf32(bR[j].x); bd[j*32+1] = f2tf32(bR[j].y);
                bd[j*32+2] = f2tf32(bR[j].z); bd[j*32+3] = f2tf32(bR[j].w);
            }
            __syncthreads();
        }
    }

    #pragma unroll
    for (int mi = 0; mi < 4; mi++) {
        const int row = by * GBM + wm * 64 + mi * 16 + fr;
        #pragma unroll
        for (int ni = 0; ni < 4; ni++) {
            const int lcol = wn * 32 + ni * 8 + fc * 2;
            const int col  = bx * GBN + lcol;
            float2 o0, o1;
            o0.x = acc[mi][ni][0] + biass[lcol];
            o0.y = acc[mi][ni][1] + biass[lcol + 1];
            o1.x = acc[mi][ni][2] + biass[lcol];
            o1.y = acc[mi][ni][3] + biass[lcol + 1];
            *(float2*)(C + (size_t)row * N + col)       = o0;
            *(float2*)(C + (size_t)(row + 8) * N + col) = o1;
        }
    }
}

// ---------------------------------------------------------------------------
// Flash attention v3: tf32 mma.sync for both S = Q@K^T and O += P@V.
// Block 256 threads = 8 warps; q-tile 128 (16 rows/warp), k-tile 64.
// Softmax warp-local (each warp owns whole rows). P routed via smem (tf32).
// Smem: Qs[128][68], Ks[64][68], Vs[64][68], Ps[128][68]  (u32/tf32) = 102KB.
// ---------------------------------------------------------------------------
#define AST 68
#define ATTN_W (128 * AST + 64 * AST + 64 * AST + 128 * AST)
#define ATTN_SMEM_B (ATTN_W * 4)   // 104448 bytes

__global__ __launch_bounds__(256, 2)
void flash_attn_mma(const float* __restrict__ qkv, float* __restrict__ ctx)
{
    extern __shared__ uint32_t sw[];
    uint32_t* Qs = sw;                       // [128][AST]
    uint32_t* Ks = Qs + 128 * AST;           // [64][AST]   natural [k][d]
    uint32_t* Vs = Ks + 64 * AST;            // [64][AST]   natural [k][d]
    uint32_t* Ps = Vs + 64 * AST;            // [128][AST]  [q][k]

    const int qt = blockIdx.x;
    const int h  = blockIdx.y;
    const int b  = blockIdx.z;
    const int tid  = threadIdx.x;
    const int w    = tid >> 5;
    const int lane = tid & 31;
    const int fr   = lane >> 2;
    const int fc   = lane & 3;

    const int q_token0 = b * SS + qt * 128;
    const int hoff = h * HDIM;

    // ---- load Q tile (tf32-converted) ----
    {
        const int r  = tid >> 1;
        const int f0 = (tid & 1) * 32;
        const float* gq = qkv + (size_t)(q_token0 + r) * TD + hoff + f0;
        uint32_t* dst = Qs + r * AST + f0;
        #pragma unroll
        for (int j = 0; j < 8; j++) {
            float4 v = *(const float4*)(gq + j * 4);
            uint4 t;
            t.x = f2tf32(v.x); t.y = f2tf32(v.y);
            t.z = f2tf32(v.z); t.w = f2tf32(v.w);
            *(uint4*)(dst + j * 4) = t;
        }
    }

    float o[8][4];
    #pragma unroll
    for (int nb = 0; nb < 8; nb++)
        #pragma unroll
        for (int v = 0; v < 4; v++) o[nb][v] = 0.f;
    float m0 = -INFINITY, m1 = -INFINITY, l0 = 0.f, l1 = 0.f;

    const int kr = tid >> 2;            // 0..63
    const int kf = (tid & 3) * 16;

    const uint32_t* Aq = Qs + (w * 16) * AST;
    uint32_t* Pw = Ps + (w * 16) * AST;

    for (int jt = 0; jt < SS / 64; jt++) {
        __syncthreads();   // previous iteration done reading Ks/Vs

        // ---- load K, V tiles (natural [k][d], tf32) ----
        {
            const float* gk = qkv + (size_t)(b * SS + jt * 64 + kr) * TD + DD + hoff + kf;
            const float* gv = gk + DD;
            uint32_t* kd = Ks + kr * AST + kf;
            uint32_t* vd = Vs + kr * AST + kf;
            #pragma unroll
            for (int j = 0; j < 4; j++) {
                float4 kv = *(const float4*)(gk + j * 4);
                uint4 t;
                t.x = f2tf32(kv.x); t.y = f2tf32(kv.y);
                t.z = f2tf32(kv.z); t.w = f2tf32(kv.w);
                *(uint4*)(kd + j * 4) = t;
                float4 vv = *(const float4*)(gv + j * 4);
                uint4 u;
                u.x = f2tf32(vv.x); u.y = f2tf32(vv.y);
                u.z = f2tf32(vv.z); u.w = f2tf32(vv.w);
                *(uint4*)(vd + j * 4) = u;
            }
        }
        __syncthreads();

        // ---- S = Q @ K^T : warp computes rows [16w,16w+16) x 64 cols ----
        float s[8][4];
        #pragma unroll
        for (int nb = 0; nb < 8; nb++)
            #pragma unroll
            for (int v = 0; v < 4; v++) s[nb][v] = 0.f;

        #pragma unroll
        for (int ks = 0; ks < 8; ks++) {
            uint32_t a[4];
            const uint32_t* ap = Aq + fr * AST + ks * 8 + fc;
            a[0] = ap[0];
            a[1] = ap[8 * AST];
            a[2] = ap[4];
            a[3] = ap[8 * AST + 4];
            #pragma unroll
            for (int nb = 0; nb < 8; nb++) {
                const uint32_t* bp = Ks + (nb * 8 + fr) * AST + ks * 8 + fc;
                uint32_t bb[2];
                bb[0] = bp[0];
                bb[1] = bp[4];
                mma_tf32(s[nb], a, bb);
            }
        }

        // ---- online softmax (rows fr and fr+8, warp-local) ----
        float mx0 = -INFINITY, mx1 = -INFINITY;
        #pragma unroll
        for (int nb = 0; nb < 8; nb++) {
            mx0 = fmaxf(mx0, fmaxf(s[nb][0], s[nb][1]));
            mx1 = fmaxf(mx1, fmaxf(s[nb][2], s[nb][3]));
        }
        mx0 *= 0.125f; mx1 *= 0.125f;
        mx0 = fmaxf(mx0, __shfl_xor_sync(0xffffffffu, mx0, 1));
        mx0 = fmaxf(mx0, __shfl_xor_sync(0xffffffffu, mx0, 2));
        mx1 = fmaxf(mx1, __shfl_xor_sync(0xffffffffu, mx1, 1));
        mx1 = fmaxf(mx1, __shfl_xor_sync(0xffffffffu, mx1, 2));

        const float mn0 = fmaxf(m0, mx0);
        const float mn1 = fmaxf(m1, mx1);
        const float alpha0 = __expf(m0 - mn0);
        const float alpha1 = __expf(m1 - mn1);

        float sum0 = 0.f, sum1 = 0.f;
        #pragma unroll
        for (int nb = 0; nb < 8; nb++) {
            float p00 = __expf(fmaf(s[nb][0], 0.125f, -mn0));
            float p01 = __expf(fmaf(s[nb][1], 0.125f, -mn0));
            float p10 = __expf(fmaf(s[nb][2], 0.125f, -mn1));
            float p11 = __expf(fmaf(s[nb][3], 0.125f, -mn1));
            sum0 += p00 + p01;
            sum1 += p10 + p11;
            uint2 w0; w0.x = f2tf32(p00); w0.y = f2tf32(p01);
            uint2 w1; w1.x = f2tf32(p10); w1.y = f2tf32(p11);
            *(uint2*)(Pw + fr * AST + nb * 8 + 2 * fc)       = w0;
            *(uint2*)(Pw + (fr + 8) * AST + nb * 8 + 2 * fc) = w1;
        }
        sum0 += __shfl_xor_sync(0xffffffffu, sum0, 1);
        sum0 += __shfl_xor_sync(0xffffffffu, sum0, 2);
        sum1 += __shfl_xor_sync(0xffffffffu, sum1, 1);
        sum1 += __shfl_xor_sync(0xffffffffu, sum1, 2);

        l0 = l0 * alpha0 + sum0;
        l1 = l1 * alpha1 + sum1;
        m0 = mn0; m1 = mn1;

        #pragma unroll
        for (int nb = 0; nb < 8; nb++) {
            o[nb][0] *= alpha0; o[nb][1] *= alpha0;
            o[nb][2] *= alpha1; o[nb][3] *= alpha1;
        }
        __syncthreads();   // Ps visible (cross-lane reads via smem)

        // ---- O += P @ V ----
        #pragma unroll
        for (int ks = 0; ks < 8; ks++) {
            uint32_t a[4];
            const uint32_t* ap = Pw + fr * AST + ks * 8 + fc;
            a[0] = ap[0];
            a[1] = ap[8 * AST];
            a[2] = ap[4];
            a[3] = ap[8 * AST + 4];
            #pragma unroll
            for (int nb = 0; nb < 8; nb++) {
                const uint32_t* bp = Vs + (ks * 8 + fc) * AST + nb * 8 + fr;
                uint32_t bb[2];
                bb[0] = bp[0];
                bb[1] = bp[4 * AST];
                mma_tf32(o[nb], a, bb);
            }
        }
    }

    // ---- epilogue ----
    const float inv0 = 1.f / l0;
    const float inv1 = 1.f / l1;
    const int row0 = q_token0 + w * 16 + fr;
    #pragma unroll
    for (int nb = 0; nb < 8; nb++) {
        const int col = hoff + nb * 8 + 2 * fc;
        float2 e0, e1;
        e0.x = o[nb][0] * inv0; e0.y = o[nb][1] * inv0;
        e1.x = o[nb][2] * inv1; e1.y = o[nb][3] * inv1;
        *(float2*)(ctx + (size_t)row0 * DD + col)       = e0;
        *(float2*)(ctx + (size_t)(row0 + 8) * DD + col) = e1;
    }
}

// ---------------------------------------------------------------------------
// Launch
// ---------------------------------------------------------------------------
extern "C" void kernel_launch(void* const* d_in, const int* in_sizes, int n_in,
                              void* d_out, int out_size)
{
    const float* x     = (const float*)d_in[0];
    const float* Wqkv  = (const float*)d_in[1];
    const float* bqkv  = (const float*)d_in[2];
    const float* Wproj = (const float*)d_in[3];
    const float* bproj = (const float*)d_in[4];
    float* out = (float*)d_out;

    float* qkvp = nullptr;
    float* ctxp = nullptr;
    cudaGetSymbolAddress((void**)&qkvp, g_qkv);
    cudaGetSymbolAddress((void**)&ctxp, g_ctx);

    static bool attr_set = false;
    if (!attr_set) {
        cudaFuncSetAttribute(flash_attn_mma,
                             cudaFuncAttributeMaxDynamicSharedMemorySize, ATTN_SMEM_B);
        cudaFuncSetAttribute(mma_gemm_bias,
                             cudaFuncAttributeMaxDynamicSharedMemorySize, GEMM_SMEM_B);
        attr_set = true;
    }

    // 1) QKV projection: [4096,1024] @ [1024,3072] + bias
    {
        dim3 grid(TD / GBN, TOK / GBM);   // (24, 32)
        mma_gemm_bias<<<grid, 256, GEMM_SMEM_B>>>(x, Wqkv, bqkv, qkvp, TOK, TD, DD);
    }

    // 2) Attention
    {
        dim3 grid(SS / 128, HH, BB);      // (16, 16, 2)
        flash_attn_mma<<<grid, 256, ATTN_SMEM_B>>>(qkvp, ctxp);
    }

    // 3) Output projection: [4096,1024] @ [1024,1024] + bias
    {
        dim3 grid(DD / GBN, TOK / GBM);   // (8, 32)
        mma_gemm_bias<<<grid, 256, GEMM_SMEM_B>>>(ctxp, Wproj, bproj, out, TOK, DD, DD);
    }
}

// round 17
// speedup vs baseline: 5.1407x; 1.0562x over previous
#include <cuda_runtime.h>
#include <cuda_bf16.h>
#include <math.h>
#include <stdint.h>

// Problem constants
#define BB   2
#define SS   2048
#define DD   1024
#define HH   16
#define HDIM 64
#define TOK  (BB * SS)        // 4096 tokens
#define TD   (3 * DD)         // 3072

// ---------------------------------------------------------------------------
// Scratch
// ---------------------------------------------------------------------------
__device__ float g_qkv[(size_t)TOK * TD];     // 48 MB (tf32-rounded by GEMM1 epilogue)
__device__ float g_ctx[(size_t)TOK * DD];     // 16 MB (tf32-rounded by attention epilogue)
__device__ float g_xr[(size_t)TOK * DD];      // 16 MB tf32-rounded x
__device__ float g_wqkvr[(size_t)DD * TD];    // 12 MB tf32-rounded Wqkv
__device__ float g_wprojr[(size_t)DD * DD];   //  4 MB tf32-rounded Wproj

__device__ __forceinline__ uint32_t f2tf32(float v) {
    uint32_t r;
    asm("cvt.rna.tf32.f32 %0, %1;" : "=r"(r) : "f"(v));
    return r;
}

__device__ __forceinline__ void mma_tf32(float* d, const uint32_t* a, const uint32_t* b) {
    asm volatile(
        "mma.sync.aligned.m16n8k8.row.col.f32.tf32.tf32.f32 "
        "{%0,%1,%2,%3}, {%4,%5,%6,%7}, {%8,%9}, {%0,%1,%2,%3};"
        : "+f"(d[0]), "+f"(d[1]), "+f"(d[2]), "+f"(d[3])
        : "r"(a[0]), "r"(a[1]), "r"(a[2]), "r"(a[3]), "r"(b[0]), "r"(b[1]));
}

__device__ __forceinline__ void cp16(uint32_t smem_u32, const void* gptr) {
    asm volatile("cp.async.ca.shared.global [%0], [%1], 16;"
                 :: "r"(smem_u32), "l"(gptr) : "memory");
}

// ---------------------------------------------------------------------------
// Pre-pass: round fp32 -> tf32-in-fp32 (rna), elementwise. n % 4 == 0.
// ---------------------------------------------------------------------------
__global__ __launch_bounds__(256)
void round_tf32_kernel(const float* __restrict__ a, float* __restrict__ b, int n)
{
    int i = (blockIdx.x * 256 + threadIdx.x) * 4;
    if (i < n) {
        float4 v = *(const float4*)(a + i);
        uint4 t;
        t.x = f2tf32(v.x); t.y = f2tf32(v.y);
        t.z = f2tf32(v.z); t.w = f2tf32(v.w);
        *(uint4*)(b + i) = t;
    }
}

// ---------------------------------------------------------------------------
// mma.sync tf32 GEMM + bias, cp.async 3-stage pipeline.
// Inputs A,B must be pre-rounded to tf32. round_out=1 rounds C (for tf32
// consumers), 0 stores raw fp32.
// CTA 128x128, BK=32, 256 threads = 8 warps (2M x 4N).
// ---------------------------------------------------------------------------
#define GBM 128
#define GBN 128
#define GBK 32
#define ASTR 36
#define BSTR 136
#define NSTAGE 3

#define A_BUF_W (GBM * ASTR)                  // 4608 words
#define B_BUF_W (GBK * BSTR)                  // 4352 words
#define GEMM_SMEM_W (NSTAGE * (A_BUF_W + B_BUF_W) + GBN)
#define GEMM_SMEM_B (GEMM_SMEM_W * 4)         // 108032 bytes

__global__ __launch_bounds__(256)
void mma_gemm_bias3(const float* __restrict__ A, const float* __restrict__ B,
                    const float* __restrict__ bias, float* __restrict__ C,
                    int M, int N, int K, int round_out)
{
    extern __shared__ uint32_t smw[];
    float* biass = (float*)(smw + NSTAGE * (A_BUF_W + B_BUF_W));
    const uint32_t smem_base = (uint32_t)__cvta_generic_to_shared(smw);

    const int tid  = threadIdx.x;
    const int wid  = tid >> 5;
    const int lane = tid & 31;
    const int wm   = wid & 1;
    const int wn   = wid >> 1;
    const int bx   = blockIdx.x;
    const int by   = blockIdx.y;

    if (tid < GBN) biass[tid] = bias[bx * GBN + tid];

    const float* Ag = A + (size_t)(by * GBM) * K;
    const float* Bg = B + bx * GBN;
    const int nchunks = K / GBK;

    // issue one K-chunk stage: A tile 128x32 (16KB) + B tile 32x128 (16KB)
    auto issue_stage = [&](int c) {
        const int st = c % NSTAGE;
        const float* Asrc = Ag + c * GBK;
        const uint32_t Adst = smem_base + (uint32_t)(st * A_BUF_W) * 4u;
        #pragma unroll
        for (int j = 0; j < 4; j++) {
            const int u = tid + j * 256;          // 0..1023
            const int row = u >> 3;               // 0..127
            const int k4  = (u & 7) * 4;          // 0,4,..28
            cp16(Adst + (uint32_t)(row * ASTR + k4) * 4u,
                 Asrc + (size_t)row * K + k4);
        }
        const float* Bsrc = Bg + (size_t)(c * GBK) * N;
        const uint32_t Bdst = smem_base + (uint32_t)(NSTAGE * A_BUF_W + st * B_BUF_W) * 4u;
        #pragma unroll
        for (int j = 0; j < 4; j++) {
            const int u = tid + j * 256;
            const int k  = u >> 5;                // 0..31
            const int n4 = (u & 31) * 4;          // 0,4,..124
            cp16(Bdst + (uint32_t)(k * BSTR + n4) * 4u,
                 Bsrc + (size_t)k * N + n4);
        }
        asm volatile("cp.async.commit_group;" ::: "memory");
    };

    issue_stage(0);
    if (nchunks > 1) issue_stage(1);

    float acc[4][4][4];
    #pragma unroll
    for (int mi = 0; mi < 4; mi++)
        #pragma unroll
        for (int ni = 0; ni < 4; ni++)
            #pragma unroll
            for (int v = 0; v < 4; v++) acc[mi][ni][v] = 0.f;

    const int fr = lane >> 2;
    const int fc = lane & 3;

    for (int c = 0; c < nchunks; c++) {
        if (c + 1 < nchunks) asm volatile("cp.async.wait_group 1;" ::: "memory");
        else                 asm volatile("cp.async.wait_group 0;" ::: "memory");
        __syncthreads();   // stage c ready; all warps done with buffer (c)%3's previous life

        if (c + 2 < nchunks) issue_stage(c + 2);

        const uint32_t* Ab = smw + (c % NSTAGE) * A_BUF_W + (wm * 64) * ASTR;
        const uint32_t* Bb = smw + NSTAGE * A_BUF_W + (c % NSTAGE) * B_BUF_W + wn * 32;
        #pragma unroll
        for (int ks = 0; ks < 4; ks++) {
            const int k = ks * 8 + fc;
            uint32_t afr[4][4], bfr[4][2];
            #pragma unroll
            for (int mi = 0; mi < 4; mi++) {
                const uint32_t* p = Ab + (mi * 16 + fr) * ASTR + k;
                afr[mi][0] = p[0];
                afr[mi][1] = p[8 * ASTR];
                afr[mi][2] = p[4];
                afr[mi][3] = p[8 * ASTR + 4];
            }
            #pragma unroll
            for (int ni = 0; ni < 4; ni++) {
                const uint32_t* q = Bb + k * BSTR + ni * 8 + fr;
                bfr[ni][0] = q[0];
                bfr[ni][1] = q[4 * BSTR];
            }
            #pragma unroll
            for (int mi = 0; mi < 4; mi++)
                #pragma unroll
                for (int ni = 0; ni < 4; ni++)
                    mma_tf32(acc[mi][ni], afr[mi], bfr[ni]);
        }
    }

    // ---- epilogue: acc + bias -> C (optionally tf32-rounded) ----
    #pragma unroll
    for (int mi = 0; mi < 4; mi++) {
        const int row = by * GBM + wm * 64 + mi * 16 + fr;
        #pragma unroll
        for (int ni = 0; ni < 4; ni++) {
            const int lcol = wn * 32 + ni * 8 + fc * 2;
            const int col  = bx * GBN + lcol;
            float v0 = acc[mi][ni][0] + biass[lcol];
            float v1 = acc[mi][ni][1] + biass[lcol + 1];
            float v2 = acc[mi][ni][2] + biass[lcol];
            float v3 = acc[mi][ni][3] + biass[lcol + 1];
            if (round_out) {
                v0 = __uint_as_float(f2tf32(v0));
                v1 = __uint_as_float(f2tf32(v1));
                v2 = __uint_as_float(f2tf32(v2));
                v3 = __uint_as_float(f2tf32(v3));
            }
            float2 o0 = make_float2(v0, v1);
            float2 o1 = make_float2(v2, v3);
            *(float2*)(C + (size_t)row * N + col)       = o0;
            *(float2*)(C + (size_t)(row + 8) * N + col) = o1;
        }
    }
}

// ---------------------------------------------------------------------------
// Flash attention (tf32 mma.sync, R12 design). Inputs pre-rounded -> no cvt
// on Q/K/V loads. Epilogue rounds ctx for the tf32-consuming proj GEMM.
// ---------------------------------------------------------------------------
#define AST 68
#define ATTN_W (128 * AST + 64 * AST + 64 * AST + 128 * AST)
#define ATTN_SMEM_B (ATTN_W * 4)   // 104448 bytes

__global__ __launch_bounds__(256, 2)
void flash_attn_mma(const float* __restrict__ qkv, float* __restrict__ ctx)
{
    extern __shared__ uint32_t sw[];
    uint32_t* Qs = sw;                       // [128][AST]
    uint32_t* Ks = Qs + 128 * AST;           // [64][AST]   natural [k][d]
    uint32_t* Vs = Ks + 64 * AST;            // [64][AST]   natural [k][d]
    uint32_t* Ps = Vs + 64 * AST;            // [128][AST]  [q][k]

    const int qt = blockIdx.x;
    const int h  = blockIdx.y;
    const int b  = blockIdx.z;
    const int tid  = threadIdx.x;
    const int w    = tid >> 5;
    const int lane = tid & 31;
    const int fr   = lane >> 2;
    const int fc   = lane & 3;

    const int q_token0 = b * SS + qt * 128;
    const int hoff = h * HDIM;

    // ---- load Q tile (already tf32) ----
    {
        const int r  = tid >> 1;
        const int f0 = (tid & 1) * 32;
        const uint32_t* gq = (const uint32_t*)(qkv + (size_t)(q_token0 + r) * TD + hoff + f0);
        uint32_t* dst = Qs + r * AST + f0;
        #pragma unroll
        for (int j = 0; j < 8; j++)
            *(uint4*)(dst + j * 4) = *(const uint4*)(gq + j * 4);
    }

    float o[8][4];
    #pragma unroll
    for (int nb = 0; nb < 8; nb++)
        #pragma unroll
        for (int v = 0; v < 4; v++) o[nb][v] = 0.f;
    float m0 = -INFINITY, m1 = -INFINITY, l0 = 0.f, l1 = 0.f;

    const int kr = tid >> 2;            // 0..63
    const int kf = (tid & 3) * 16;

    const uint32_t* Aq = Qs + (w * 16) * AST;
    uint32_t* Pw = Ps + (w * 16) * AST;

    for (int jt = 0; jt < SS / 64; jt++) {
        __syncthreads();   // previous iteration done reading Ks/Vs

        // ---- load K, V tiles (already tf32) ----
        {
            const uint32_t* gk = (const uint32_t*)(qkv + (size_t)(b * SS + jt * 64 + kr) * TD + DD + hoff + kf);
            const uint32_t* gv = gk + DD;
            uint32_t* kd = Ks + kr * AST + kf;
            uint32_t* vd = Vs + kr * AST + kf;
            #pragma unroll
            for (int j = 0; j < 4; j++) {
                *(uint4*)(kd + j * 4) = *(const uint4*)(gk + j * 4);
                *(uint4*)(vd + j * 4) = *(const uint4*)(gv + j * 4);
            }
        }
        __syncthreads();

        // ---- S = Q @ K^T ----
        float s[8][4];
        #pragma unroll
        for (int nb = 0; nb < 8; nb++)
            #pragma unroll
            for (int v = 0; v < 4; v++) s[nb][v] = 0.f;

        #pragma unroll
        for (int ks = 0; ks < 8; ks++) {
            uint32_t a[4];
            const uint32_t* ap = Aq + fr * AST + ks * 8 + fc;
            a[0] = ap[0];
            a[1] = ap[8 * AST];
            a[2] = ap[4];
            a[3] = ap[8 * AST + 4];
            #pragma unroll
            for (int nb = 0; nb < 8; nb++) {
                const uint32_t* bp = Ks + (nb * 8 + fr) * AST + ks * 8 + fc;
                uint32_t bb[2];
                bb[0] = bp[0];
                bb[1] = bp[4];
                mma_tf32(s[nb], a, bb);
            }
        }

        // ---- online softmax (rows fr and fr+8, warp-local) ----
        float mx0 = -INFINITY, mx1 = -INFINITY;
        #pragma unroll
        for (int nb = 0; nb < 8; nb++) {
            mx0 = fmaxf(mx0, fmaxf(s[nb][0], s[nb][1]));
            mx1 = fmaxf(mx1, fmaxf(s[nb][2], s[nb][3]));
        }
        mx0 *= 0.125f; mx1 *= 0.125f;
        mx0 = fmaxf(mx0, __shfl_xor_sync(0xffffffffu, mx0, 1));
        mx0 = fmaxf(mx0, __shfl_xor_sync(0xffffffffu, mx0, 2));
        mx1 = fmaxf(mx1, __shfl_xor_sync(0xffffffffu, mx1, 1));
        mx1 = fmaxf(mx1, __shfl_xor_sync(0xffffffffu, mx1, 2));

        const float mn0 = fmaxf(m0, mx0);
        const float mn1 = fmaxf(m1, mx1);
        const float alpha0 = __expf(m0 - mn0);
        const float alpha1 = __expf(m1 - mn1);

        float sum0 = 0.f, sum1 = 0.f;
        #pragma unroll
        for (int nb = 0; nb < 8; nb++) {
            float p00 = __expf(fmaf(s[nb][0], 0.125f, -mn0));
            float p01 = __expf(fmaf(s[nb][1], 0.125f, -mn0));
            float p10 = __expf(fmaf(s[nb][2], 0.125f, -mn1));
            float p11 = __expf(fmaf(s[nb][3], 0.125f, -mn1));
            sum0 += p00 + p01;
            sum1 += p10 + p11;
            uint2 w0; w0.x = f2tf32(p00); w0.y = f2tf32(p01);
            uint2 w1; w1.x = f2tf32(p10); w1.y = f2tf32(p11);
            *(uint2*)(Pw + fr * AST + nb * 8 + 2 * fc)       = w0;
            *(uint2*)(Pw + (fr + 8) * AST + nb * 8 + 2 * fc) = w1;
        }
        sum0 += __shfl_xor_sync(0xffffffffu, sum0, 1);
        sum0 += __shfl_xor_sync(0xffffffffu, sum0, 2);
        sum1 += __shfl_xor_sync(0xffffffffu, sum1, 1);
        sum1 += __shfl_xor_sync(0xffffffffu, sum1, 2);

        l0 = l0 * alpha0 + sum0;
        l1 = l1 * alpha1 + sum1;
        m0 = mn0; m1 = mn1;

        #pragma unroll
        for (int nb = 0; nb < 8; nb++) {
            o[nb][0] *= alpha0; o[nb][1] *= alpha0;
            o[nb][2] *= alpha1; o[nb][3] *= alpha1;
        }
        __syncthreads();   // Ps visible

        // ---- O += P @ V ----
        #pragma unroll
        for (int ks = 0; ks < 8; ks++) {
            uint32_t a[4];
            const uint32_t* ap = Pw + fr * AST + ks * 8 + fc;
            a[0] = ap[0];
            a[1] = ap[8 * AST];
            a[2] = ap[4];
            a[3] = ap[8 * AST + 4];
            #pragma unroll
            for (int nb = 0; nb < 8; nb++) {
                const uint32_t* bp = Vs + (ks * 8 + fc) * AST + nb * 8 + fr;
                uint32_t bb[2];
                bb[0] = bp[0];
                bb[1] = bp[4 * AST];
                mma_tf32(o[nb], a, bb);
            }
        }
    }

    // ---- epilogue (tf32-rounded for the proj GEMM) ----
    const float inv0 = 1.f / l0;
    const float inv1 = 1.f / l1;
    const int row0 = q_token0 + w * 16 + fr;
    #pragma unroll
    for (int nb = 0; nb < 8; nb++) {
        const int col = hoff + nb * 8 + 2 * fc;
        uint2 e0, e1;
        e0.x = f2tf32(o[nb][0] * inv0); e0.y = f2tf32(o[nb][1] * inv0);
        e1.x = f2tf32(o[nb][2] * inv1); e1.y = f2tf32(o[nb][3] * inv1);
        *(uint2*)(ctx + (size_t)row0 * DD + col)       = e0;
        *(uint2*)(ctx + (size_t)(row0 + 8) * DD + col) = e1;
    }
}

// ---------------------------------------------------------------------------
// Launch
// ---------------------------------------------------------------------------
extern "C" void kernel_launch(void* const* d_in, const int* in_sizes, int n_in,
                              void* d_out, int out_size)
{
    const float* x     = (const float*)d_in[0];
    const float* Wqkv  = (const float*)d_in[1];
    const float* bqkv  = (const float*)d_in[2];
    const float* Wproj = (const float*)d_in[3];
    const float* bproj = (const float*)d_in[4];
    float* out = (float*)d_out;

    float *qkvp = nullptr, *ctxp = nullptr, *xr = nullptr, *wqkvr = nullptr, *wprojr = nullptr;
    cudaGetSymbolAddress((void**)&qkvp,   g_qkv);
    cudaGetSymbolAddress((void**)&ctxp,   g_ctx);
    cudaGetSymbolAddress((void**)&xr,     g_xr);
    cudaGetSymbolAddress((void**)&wqkvr,  g_wqkvr);
    cudaGetSymbolAddress((void**)&wprojr, g_wprojr);

    static bool attr_set = false;
    if (!attr_set) {
        cudaFuncSetAttribute(flash_attn_mma,
                             cudaFuncAttributeMaxDynamicSharedMemorySize, ATTN_SMEM_B);
        cudaFuncSetAttribute(mma_gemm_bias3,
                             cudaFuncAttributeMaxDynamicSharedMemorySize, GEMM_SMEM_B);
        attr_set = true;
    }

    // 0) Pre-round inputs to tf32 (rna)
    {
        const int nx = TOK * DD, nq = DD * TD, np = DD * DD;
        round_tf32_kernel<<<nx / 1024, 256>>>(x,     xr,     nx);
        round_tf32_kernel<<<nq / 1024, 256>>>(Wqkv,  wqkvr,  nq);
        round_tf32_kernel<<<np / 1024, 256>>>(Wproj, wprojr, np);
    }

    // 1) QKV projection: rounds output for attention
    {
        dim3 grid(TD / GBN, TOK / GBM);   // (24, 32)
        mma_gemm_bias3<<<grid, 256, GEMM_SMEM_B>>>(xr, wqkvr, bqkv, qkvp, TOK, TD, DD, 1);
    }

    // 2) Attention (rounds ctx for proj)
    {
        dim3 grid(SS / 128, HH, BB);      // (16, 16, 2)
        flash_attn_mma<<<grid, 256, ATTN_SMEM_B>>>(qkvp, ctxp);
    }

    // 3) Output projection: raw fp32 out
    {
        dim3 grid(DD / GBN, TOK / GBM);   // (8, 32)
        mma_gemm_bias3<<<grid, 256, GEMM_SMEM_B>>>(ctxp, wprojr, bproj, out, TOK, DD, DD, 0);
    }
}